// round 1
// baseline (speedup 1.0000x reference)
#include <cuda_runtime.h>
#include <math.h>

#define TT 512
#define BB 64
#define II 512
#define HH 512
#define GG 2048   // 4*H

// ---- scratch (static __device__ allocations only; no cudaMalloc allowed) ----
__device__ float g_WT_ih[2][II][GG];          // 8 MB   W_ih transposed: [k][n]
__device__ float g_WT_hh[2][HH][GG];          // 8 MB   W_hh transposed: [k][n]
__device__ float g_xp[2][TT][BB][GG];         // 512 MB x-projection (both dirs)
__device__ float g_c[2][BB][HH];              // 256 KB cell state

// ============================================================================
// Weight transpose: src [2048,512] row-major -> dst [512,2048] row-major
// z: 0=ih_f, 1=ih_b, 2=hh_f, 3=hh_b
// ============================================================================
__global__ void prep_transpose(const float* __restrict__ s0,
                               const float* __restrict__ s1,
                               const float* __restrict__ s2,
                               const float* __restrict__ s3) {
    __shared__ float tile[32][33];
    const float* src;
    float* dst;
    switch (blockIdx.z) {
        case 0:  src = s0; dst = &g_WT_ih[0][0][0]; break;
        case 1:  src = s1; dst = &g_WT_ih[1][0][0]; break;
        case 2:  src = s2; dst = &g_WT_hh[0][0][0]; break;
        default: src = s3; dst = &g_WT_hh[1][0][0]; break;
    }
    const int n0 = blockIdx.x * 32;  // src row block (n, 0..2047)
    const int k0 = blockIdx.y * 32;  // src col block (k, 0..511)
    const int tx = threadIdx.x, ty = threadIdx.y;  // 32 x 8
#pragma unroll
    for (int i = 0; i < 32; i += 8)
        tile[ty + i][tx] = src[(size_t)(n0 + ty + i) * II + k0 + tx];
    __syncthreads();
#pragma unroll
    for (int i = 0; i < 32; i += 8)
        dst[(size_t)(k0 + ty + i) * GG + n0 + tx] = tile[tx][ty + i];
}

// ============================================================================
// Copy c0 into cell-state scratch
// ============================================================================
__global__ void init_c(const float* __restrict__ c0) {
    const int i = blockIdx.x * blockDim.x + threadIdx.x;  // 65536 total
    (&g_c[0][0][0])[i] = c0[i];
}

// ============================================================================
// x-projection GEMM:  g_xp[dir][t][b][n] = bias[n] + sum_k x[t,b,k]*WT_ih[dir][k][n]
// A = x as [32768, 512] row-major, B = WT_ih[dir] [512, 2048] row-major
// Tile 128x64x16, 256 threads, 8x4 microtile.
// ============================================================================
__global__ __launch_bounds__(256) void xproj_kernel(const float* __restrict__ A,
                                                    const float* __restrict__ bias_f,
                                                    const float* __restrict__ bias_b) {
    const int dir = blockIdx.z;
    const float* __restrict__ Bm = &g_WT_ih[dir][0][0];
    const float* __restrict__ bias = dir ? bias_b : bias_f;
    float* __restrict__ C = &g_xp[dir][0][0][0];

    __shared__ float As[16][132];  // transposed A tile [k][m], padded
    __shared__ float Bs[16][64];

    const int tid  = threadIdx.x;
    const int row0 = blockIdx.x * 128;
    const int col0 = blockIdx.y * 64;
    const int trow = (tid >> 4) * 8;
    const int tcol = (tid & 15) * 4;

    const int a_r = tid >> 2;          // 0..63  (rows a_r and a_r+64)
    const int a_c = (tid & 3) * 4;     // 0,4,8,12
    const int b_r = tid >> 4;          // 0..15
    const int b_c = (tid & 15) * 4;    // 0..60

    float acc[8][4];
#pragma unroll
    for (int i = 0; i < 8; i++)
#pragma unroll
        for (int j = 0; j < 4; j++) acc[i][j] = 0.f;

    for (int k0 = 0; k0 < II; k0 += 16) {
        float4 av0 = *(const float4*)&A[(size_t)(row0 + a_r) * II + k0 + a_c];
        float4 av1 = *(const float4*)&A[(size_t)(row0 + a_r + 64) * II + k0 + a_c];
        As[a_c + 0][a_r] = av0.x;
        As[a_c + 1][a_r] = av0.y;
        As[a_c + 2][a_r] = av0.z;
        As[a_c + 3][a_r] = av0.w;
        As[a_c + 0][a_r + 64] = av1.x;
        As[a_c + 1][a_r + 64] = av1.y;
        As[a_c + 2][a_r + 64] = av1.z;
        As[a_c + 3][a_r + 64] = av1.w;
        float4 bv = *(const float4*)&Bm[(size_t)(k0 + b_r) * GG + col0 + b_c];
        *(float4*)&Bs[b_r][b_c] = bv;
        __syncthreads();
#pragma unroll
        for (int kk = 0; kk < 16; kk++) {
            float4 a0 = *(const float4*)&As[kk][trow];
            float4 a1 = *(const float4*)&As[kk][trow + 4];
            float4 bb = *(const float4*)&Bs[kk][tcol];
            float av[8] = {a0.x, a0.y, a0.z, a0.w, a1.x, a1.y, a1.z, a1.w};
            float bw[4] = {bb.x, bb.y, bb.z, bb.w};
#pragma unroll
            for (int i = 0; i < 8; i++)
#pragma unroll
                for (int j = 0; j < 4; j++) acc[i][j] += av[i] * bw[j];
        }
        __syncthreads();
    }

#pragma unroll
    for (int j = 0; j < 4; j++) {
        const float bj = bias[col0 + tcol + j];
#pragma unroll
        for (int i = 0; i < 8; i++)
            C[(size_t)(row0 + trow + i) * GG + col0 + tcol + j] = acc[i][j] + bj;
    }
}

// ============================================================================
// One recurrence step (both directions in one launch, gridDim.z = 2).
// grid.x: 32 h-column tiles (16 cols each -> 64 gate cols)
// grid.y: 2 batch tiles (32 rows each)
// gates[b,n] = xp[dir][t][b][n] + sum_k h_prev[b,k] * WT_hh[dir][k][n]
// then fused i/f/g/o activation, c update, h written straight into out.
// h_prev is read from `out` (previous step's launch), or h0 at step 0.
// ============================================================================
__global__ __launch_bounds__(256) void step_kernel(const float* __restrict__ h0,
                                                   float* __restrict__ out,
                                                   const int step) {
    const int dir = blockIdx.z;
    const int b0  = blockIdx.y * 32;
    const int c0  = blockIdx.x * 16;
    const int t   = dir ? (TT - 1 - step) : step;

    const float* hprev;
    int hstride;
    if (step == 0) {
        hprev = h0 + dir * (BB * HH);
        hstride = HH;
    } else {
        const int tprev = dir ? (t + 1) : (t - 1);
        hprev = out + (size_t)tprev * BB * (2 * HH) + dir * HH;
        hstride = 2 * HH;
    }

    __shared__ float As[16][34];   // h tile transposed [k][b], padded
    __shared__ float Bs[16][64];   // W tile: 4 gate strips x 16 cols
    __shared__ float Gs[32][64];   // gate preactivations staging

    const int tid = threadIdx.x;
    const int tn  = (tid & 15) * 4;   // col in [0,64)
    const int tb  = (tid >> 4) * 2;   // row in [0,32)

    const int ar = tid >> 3;          // 0..31
    const int ac = (tid & 7) * 2;     // 0..14
    const int br = tid >> 4;          // 0..15
    const int bc = (tid & 15) * 4;    // 0..60
    const int nb = (bc >> 4) * HH + c0 + (bc & 15);  // global gate col for Bs load

    float acc[2][4] = {{0.f, 0.f, 0.f, 0.f}, {0.f, 0.f, 0.f, 0.f}};

    for (int k0 = 0; k0 < HH; k0 += 16) {
        float2 hv = *(const float2*)&hprev[(size_t)(b0 + ar) * hstride + k0 + ac];
        As[ac][ar]     = hv.x;
        As[ac + 1][ar] = hv.y;
        float4 wv = *(const float4*)&g_WT_hh[dir][k0 + br][nb];
        *(float4*)&Bs[br][bc] = wv;
        __syncthreads();
#pragma unroll
        for (int kk = 0; kk < 16; kk++) {
            const float a0 = As[kk][tb];
            const float a1 = As[kk][tb + 1];
            const float4 w = *(const float4*)&Bs[kk][tn];
            acc[0][0] += a0 * w.x; acc[0][1] += a0 * w.y;
            acc[0][2] += a0 * w.z; acc[0][3] += a0 * w.w;
            acc[1][0] += a1 * w.x; acc[1][1] += a1 * w.y;
            acc[1][2] += a1 * w.z; acc[1][3] += a1 * w.w;
        }
        __syncthreads();
    }

    // add x-projection, stage gates to smem (Gs[b][gate*16 + cc])
    {
        const int gate = tn >> 4;
        const int cc   = tn & 15;
#pragma unroll
        for (int i = 0; i < 2; i++) {
            const float* xpp = &g_xp[dir][t][b0 + tb + i][gate * HH + c0 + cc];
#pragma unroll
            for (int j = 0; j < 4; j++)
                Gs[tb + i][tn + j] = acc[i][j] + xpp[j];
        }
    }
    __syncthreads();

    // elementwise LSTM cell: 512 (b,col) pairs, 2 per thread
    for (int p = tid; p < 512; p += 256) {
        const int b   = p >> 4;
        const int col = p & 15;
        const float gi = Gs[b][col];
        const float gf = Gs[b][16 + col];
        const float gg = Gs[b][32 + col];
        const float go = Gs[b][48 + col];
        const float si = 1.f / (1.f + expf(-gi));
        const float sf = 1.f / (1.f + expf(-gf));
        const float tg = tanhf(gg);
        const float so = 1.f / (1.f + expf(-go));
        float* cp = &g_c[dir][b0 + b][c0 + col];
        const float cn = sf * (*cp) + si * tg;
        *cp = cn;
        out[((size_t)t * BB + b0 + b) * (2 * HH) + dir * HH + c0 + col] = so * tanhf(cn);
    }
}

// ============================================================================
// Launch: prep (transpose + c init) -> xproj GEMM -> 512 fused step kernels.
// All launches on the capture stream; stream ordering provides the t->t+1 dep.
// ============================================================================
extern "C" void kernel_launch(void* const* d_in, const int* in_sizes, int n_in,
                              void* d_out, int out_size) {
    const float* x      = (const float*)d_in[0];
    const float* h0     = (const float*)d_in[1];
    const float* c0     = (const float*)d_in[2];
    const float* W_ih_f = (const float*)d_in[3];
    const float* W_hh_f = (const float*)d_in[4];
    const float* b_f    = (const float*)d_in[5];
    const float* W_ih_b = (const float*)d_in[6];
    const float* W_hh_b = (const float*)d_in[7];
    const float* b_b    = (const float*)d_in[8];
    float* out = (float*)d_out;

    prep_transpose<<<dim3(64, 16, 4), dim3(32, 8)>>>(W_ih_f, W_ih_b, W_hh_f, W_hh_b);
    init_c<<<256, 256>>>(c0);
    // M=32768 (T*B), N=2048, K=512 per direction
    xproj_kernel<<<dim3(32768 / 128, 2048 / 64, 2), 256>>>(x, b_f, b_b);
    for (int s = 0; s < TT; s++)
        step_kernel<<<dim3(32, 2, 2), 256>>>(h0, out, s);
}

// round 7
// speedup vs baseline: 1.5396x; 1.5396x over previous
#include <cuda_runtime.h>
#include <cstdint>
#include <math.h>

#define TT 512
#define BB 64
#define II 512
#define HH 512
#define GG 2048   // 4*H
#define NCTA 128

// ---- scratch (static __device__ allocations only) ----
__device__ float    g_WT_ih[2][II][GG];        // 8 MB   W_ih transposed [k][n] for xproj
__device__ float    g_xp[2][TT][BB][GG];       // 512 MB x-projection (both dirs)
__device__ unsigned g_ctr;                     // grid barrier counter

// ============================================================================
// Weight transpose for W_ih only: src [2048,512] -> dst [512,2048]
// ============================================================================
__global__ void prep_transpose(const float* __restrict__ s0,
                               const float* __restrict__ s1) {
    __shared__ float tile[32][33];
    const float* src = blockIdx.z ? s1 : s0;
    float* dst = &g_WT_ih[blockIdx.z][0][0];
    const int n0 = blockIdx.x * 32;
    const int k0 = blockIdx.y * 32;
    const int tx = threadIdx.x, ty = threadIdx.y;  // 32 x 8
#pragma unroll
    for (int i = 0; i < 32; i += 8)
        tile[ty + i][tx] = src[(size_t)(n0 + ty + i) * II + k0 + tx];
    __syncthreads();
#pragma unroll
    for (int i = 0; i < 32; i += 8)
        dst[(size_t)(k0 + ty + i) * GG + n0 + tx] = tile[tx][ty + i];
}

// ============================================================================
// Reset grid-barrier counter (stream-ordered before the persistent kernel)
// ============================================================================
__global__ void init_bar() { g_ctr = 0u; }

// ============================================================================
// x-projection GEMM: g_xp[dir][t][b][n] = bias[n] + sum_k x[t,b,k]*WT_ih[dir][k][n]
// ============================================================================
__global__ __launch_bounds__(256) void xproj_kernel(const float* __restrict__ A,
                                                    const float* __restrict__ bias_f,
                                                    const float* __restrict__ bias_b) {
    const int dir = blockIdx.z;
    const float* __restrict__ Bm = &g_WT_ih[dir][0][0];
    const float* __restrict__ bias = dir ? bias_b : bias_f;
    float* __restrict__ C = &g_xp[dir][0][0][0];

    __shared__ float As[16][132];
    __shared__ float Bs[16][64];

    const int tid  = threadIdx.x;
    const int row0 = blockIdx.x * 128;
    const int col0 = blockIdx.y * 64;
    const int trow = (tid >> 4) * 8;
    const int tcol = (tid & 15) * 4;

    const int a_r = tid >> 2;
    const int a_c = (tid & 3) * 4;
    const int b_r = tid >> 4;
    const int b_c = (tid & 15) * 4;

    float acc[8][4];
#pragma unroll
    for (int i = 0; i < 8; i++)
#pragma unroll
        for (int j = 0; j < 4; j++) acc[i][j] = 0.f;

    for (int k0 = 0; k0 < II; k0 += 16) {
        float4 av0 = *(const float4*)&A[(size_t)(row0 + a_r) * II + k0 + a_c];
        float4 av1 = *(const float4*)&A[(size_t)(row0 + a_r + 64) * II + k0 + a_c];
        As[a_c + 0][a_r] = av0.x;
        As[a_c + 1][a_r] = av0.y;
        As[a_c + 2][a_r] = av0.z;
        As[a_c + 3][a_r] = av0.w;
        As[a_c + 0][a_r + 64] = av1.x;
        As[a_c + 1][a_r + 64] = av1.y;
        As[a_c + 2][a_r + 64] = av1.z;
        As[a_c + 3][a_r + 64] = av1.w;
        float4 bv = *(const float4*)&Bm[(size_t)(k0 + b_r) * GG + col0 + b_c];
        *(float4*)&Bs[b_r][b_c] = bv;
        __syncthreads();
#pragma unroll
        for (int kk = 0; kk < 16; kk++) {
            float4 a0 = *(const float4*)&As[kk][trow];
            float4 a1 = *(const float4*)&As[kk][trow + 4];
            float4 bb = *(const float4*)&Bs[kk][tcol];
            float av[8] = {a0.x, a0.y, a0.z, a0.w, a1.x, a1.y, a1.z, a1.w};
            float bw[4] = {bb.x, bb.y, bb.z, bb.w};
#pragma unroll
            for (int i = 0; i < 8; i++)
#pragma unroll
                for (int j = 0; j < 4; j++) acc[i][j] += av[i] * bw[j];
        }
        __syncthreads();
    }

#pragma unroll
    for (int j = 0; j < 4; j++) {
        const float bj = bias[col0 + tcol + j];
#pragma unroll
        for (int i = 0; i < 8; i++)
            C[(size_t)(row0 + trow + i) * GG + col0 + tcol + j] = acc[i][j] + bj;
    }
}

// ============================================================================
// Persistent bidirectional LSTM recurrence.
// 128 CTAs (co-resident, 1/SM): cta 0..63 = forward, 64..127 = backward.
// CTA owns 8 h-columns -> 32 gate cols. W_hh slice smem-resident all steps.
// Grid barrier per step with proper release/acquire semantics.
// ============================================================================

// h reload: plain LDG (.cg) + STS. 64 rows x 512 cols, Hs row stride 516.
__device__ __forceinline__ void load_hs(float* Hs, const float* src, int stride, int tid) {
#pragma unroll
    for (int i = 0; i < 32; i++) {
        int j  = tid + (i << 8);   // 0..8191 float4 index
        int b  = j >> 7;           // 128 float4 per 512-col row
        int k4 = j & 127;
        float4 v;
        const float* p = src + (size_t)b * stride + k4 * 4;
        asm volatile("ld.global.cg.v4.f32 {%0,%1,%2,%3}, [%4];"
                     : "=f"(v.x), "=f"(v.y), "=f"(v.z), "=f"(v.w) : "l"(p));
        *(float4*)(Hs + b * 516 + k4 * 4) = v;
    }
}

#define SMEM_FLOATS (16384 + 64*516 + 64*32 + 512)
#define SMEM_BYTES  (SMEM_FLOATS * 4)

__global__ __launch_bounds__(256, 1) void lstm_persist(const float* __restrict__ h0,
                                                       const float* __restrict__ c0,
                                                       const float* __restrict__ Whh_f,
                                                       const float* __restrict__ Whh_b,
                                                       float* __restrict__ out) {
    extern __shared__ float sm[];
    float* Ws  = sm;                  // [512][32]
    float* Hs  = sm + 16384;          // [64][516]
    float* Gs  = Hs + 64 * 516;       // [64][32]
    float* csh = Gs + 64 * 32;        // [512]

    const int tid   = threadIdx.x;
    const int lane  = tid & 31;
    const int warp  = tid >> 5;
    const int cta   = blockIdx.x;
    const int dir   = cta >> 6;
    const int c0col = (cta & 63) << 3;    // 8 h-cols per CTA
    const int ccmp  = warp << 2;          // warp's compact col base (0..28)
    const int gcol  = ((warp >> 1) << 9) + c0col + ((warp & 1) << 2);

    const float* __restrict__ Whh = dir ? Whh_b : Whh_f;
    const float* __restrict__ xpD = &g_xp[dir][0][0][0];

    // ---- load W_hh slice into smem: Ws[k][n_compact], n = g*512+c0col+cc ----
#pragma unroll
    for (int i = 0; i < 16; i++) {
        int j  = tid + (i << 8);          // 0..4095 float4s
        int n  = j >> 7;                  // compact col 0..31
        int k4 = j & 127;
        int gn = ((n >> 3) << 9) + c0col + (n & 7);
        float4 w = *(const float4*)(Whh + (size_t)gn * HH + k4 * 4);
        int k = k4 * 4;
        Ws[(k + 0) * 32 + n] = w.x;
        Ws[(k + 1) * 32 + n] = w.y;
        Ws[(k + 2) * 32 + n] = w.z;
        Ws[(k + 3) * 32 + n] = w.w;
    }
    // ---- cell state ----
    for (int p = tid; p < 512; p += 256) {
        int b = p >> 3, cc = p & 7;
        csh[p] = c0[(size_t)dir * BB * HH + b * HH + c0col + cc];
    }
    // ---- h for step 0 ----
    load_hs(Hs, h0 + (size_t)dir * BB * HH, HH, tid);
    __syncthreads();

    for (int step = 0; step < TT; step++) {
        const int t = dir ? (TT - 1 - step) : step;

        // ---- GEMM: gates[b, 32 cols] += Hs @ Ws, thread tile 2b x 4c ----
        float a00 = 0.f, a01 = 0.f, a02 = 0.f, a03 = 0.f;
        float a10 = 0.f, a11 = 0.f, a12 = 0.f, a13 = 0.f;
        const float* hA = Hs + lane * 516;
        const float* hB = Hs + (lane + 32) * 516;
        const float* wP = Ws + ccmp;
#pragma unroll 4
        for (int k = 0; k < HH; k += 4) {
            const float4 ha = *(const float4*)(hA + k);
            const float4 hb = *(const float4*)(hB + k);
            const float4 w0 = *(const float4*)(wP + (k + 0) * 32);
            const float4 w1 = *(const float4*)(wP + (k + 1) * 32);
            const float4 w2 = *(const float4*)(wP + (k + 2) * 32);
            const float4 w3 = *(const float4*)(wP + (k + 3) * 32);
            a00 += ha.x * w0.x; a01 += ha.x * w0.y; a02 += ha.x * w0.z; a03 += ha.x * w0.w;
            a10 += hb.x * w0.x; a11 += hb.x * w0.y; a12 += hb.x * w0.z; a13 += hb.x * w0.w;
            a00 += ha.y * w1.x; a01 += ha.y * w1.y; a02 += ha.y * w1.z; a03 += ha.y * w1.w;
            a10 += hb.y * w1.x; a11 += hb.y * w1.y; a12 += hb.y * w1.z; a13 += hb.y * w1.w;
            a00 += ha.z * w2.x; a01 += ha.z * w2.y; a02 += ha.z * w2.z; a03 += ha.z * w2.w;
            a10 += hb.z * w2.x; a11 += hb.z * w2.y; a12 += hb.z * w2.z; a13 += hb.z * w2.w;
            a00 += ha.w * w3.x; a01 += ha.w * w3.y; a02 += ha.w * w3.z; a03 += ha.w * w3.w;
            a10 += hb.w * w3.x; a11 += hb.w * w3.y; a12 += hb.w * w3.z; a13 += hb.w * w3.w;
        }

        // ---- add x-projection, stage to Gs ----
        {
            const float* xpt = xpD + (size_t)t * BB * GG;
            float4 x0 = *(const float4*)(xpt + (size_t)lane * GG + gcol);
            float4 x1 = *(const float4*)(xpt + (size_t)(lane + 32) * GG + gcol);
            float4 gq;
            gq.x = a00 + x0.x; gq.y = a01 + x0.y; gq.z = a02 + x0.z; gq.w = a03 + x0.w;
            *(float4*)(Gs + lane * 32 + ccmp) = gq;
            gq.x = a10 + x1.x; gq.y = a11 + x1.y; gq.z = a12 + x1.z; gq.w = a13 + x1.w;
            *(float4*)(Gs + (lane + 32) * 32 + ccmp) = gq;
        }
        __syncthreads();

        // ---- cell update + write h ----
        for (int p = tid; p < 512; p += 256) {
            int b = p >> 3, cc = p & 7;
            const float gi = Gs[b * 32 + cc];
            const float gf = Gs[b * 32 + 8 + cc];
            const float gg = Gs[b * 32 + 16 + cc];
            const float go = Gs[b * 32 + 24 + cc];
            const float si = 1.f / (1.f + expf(-gi));
            const float sf = 1.f / (1.f + expf(-gf));
            const float tg = tanhf(gg);
            const float so = 1.f / (1.f + expf(-go));
            const float cn = sf * csh[p] + si * tg;
            csh[p] = cn;
            out[((size_t)t * BB + b) * (2 * HH) + (dir << 9) + c0col + cc] = so * tanhf(cn);
        }

        if (step == TT - 1) break;

        // ---- grid barrier with release/acquire semantics ----
        __threadfence();       // every thread orders its own h-stores
        __syncthreads();       // h-stores of all threads happen-before tid0's atom
        if (tid == 0) {
            unsigned old;
            asm volatile("atom.add.release.gpu.global.u32 %0, [%1], 1;"
                         : "=r"(old) : "l"(&g_ctr) : "memory");
            const unsigned target = (unsigned)NCTA * (unsigned)(step + 1);
            unsigned v;
            do {
                asm volatile("ld.acquire.gpu.global.u32 %0, [%1];"
                             : "=r"(v) : "l"(&g_ctr) : "memory");
            } while (v < target);
        }
        __syncthreads();       // tid0's acquire happens-before all threads' loads

        // ---- reload Hs = h(t) from out ----
        load_hs(Hs, out + (size_t)t * BB * (2 * HH) + (dir << 9), 2 * HH, tid);
        __syncthreads();
    }
}

// ============================================================================
extern "C" void kernel_launch(void* const* d_in, const int* in_sizes, int n_in,
                              void* d_out, int out_size) {
    const float* x      = (const float*)d_in[0];
    const float* h0     = (const float*)d_in[1];
    const float* c0     = (const float*)d_in[2];
    const float* W_ih_f = (const float*)d_in[3];
    const float* W_hh_f = (const float*)d_in[4];
    const float* b_f    = (const float*)d_in[5];
    const float* W_ih_b = (const float*)d_in[6];
    const float* W_hh_b = (const float*)d_in[7];
    const float* b_b    = (const float*)d_in[8];
    float* out = (float*)d_out;

    static int smem_set = 0;
    if (!smem_set) {
        cudaFuncSetAttribute(lstm_persist,
                             cudaFuncAttributeMaxDynamicSharedMemorySize, SMEM_BYTES);
        smem_set = 1;
    }

    prep_transpose<<<dim3(64, 16, 2), dim3(32, 8)>>>(W_ih_f, W_ih_b);
    init_bar<<<1, 1>>>();
    xproj_kernel<<<dim3(32768 / 128, 2048 / 64, 2), 256>>>(x, b_f, b_b);
    lstm_persist<<<NCTA, 256, SMEM_BYTES>>>(h0, c0, W_hh_f, W_hh_b, out);
}

// round 11
// speedup vs baseline: 1.8614x; 1.2090x over previous
#include <cuda_runtime.h>
#include <cuda_bf16.h>
#include <cstdint>
#include <math.h>

#define TT 512
#define BB 64
#define II 512
#define HH 512
#define GG 2048   // 4*H
#define NCTA 128

// ---- scratch (static __device__ allocations only) ----
__device__ float         g_xp[2][TT][BB][GG];   // 512 MB x-projection (both dirs)
__device__ unsigned      g_ctr;                 // grid barrier counter
__device__ __nv_bfloat16 g_xhi[TT * BB * II];   // 32 MB
__device__ __nv_bfloat16 g_xlo[TT * BB * II];   // 32 MB
__device__ __nv_bfloat16 g_whi[2][GG * II];     // 4 MB
__device__ __nv_bfloat16 g_wlo[2][GG * II];     // 4 MB

// ============================================================================
// helpers
// ============================================================================
__device__ __forceinline__ unsigned smem_u32(const void* p) {
    unsigned a;
    asm("{ .reg .u64 t; cvta.to.shared.u64 t, %1; cvt.u32.u64 %0, t; }"
        : "=r"(a) : "l"(p));
    return a;
}
__device__ __forceinline__ void cpa16(unsigned dst, const void* src) {
    asm volatile("cp.async.cg.shared.global [%0], [%1], 16;" :: "r"(dst), "l"(src));
}
__device__ __forceinline__ void ldm4(unsigned& r0, unsigned& r1, unsigned& r2,
                                     unsigned& r3, unsigned addr) {
    asm volatile("ldmatrix.sync.aligned.m8n8.x4.shared.b16 {%0,%1,%2,%3}, [%4];"
                 : "=r"(r0), "=r"(r1), "=r"(r2), "=r"(r3) : "r"(addr));
}
__device__ __forceinline__ void mma16816(float* c, const unsigned* a, const unsigned* b) {
    asm volatile(
        "mma.sync.aligned.m16n8k16.row.col.f32.bf16.bf16.f32 "
        "{%0,%1,%2,%3}, {%4,%5,%6,%7}, {%8,%9}, {%0,%1,%2,%3};"
        : "+f"(c[0]), "+f"(c[1]), "+f"(c[2]), "+f"(c[3])
        : "r"(a[0]), "r"(a[1]), "r"(a[2]), "r"(a[3]), "r"(b[0]), "r"(b[1]));
}

// ============================================================================
// hi/lo bf16 split conversion
// ============================================================================
__global__ void split_x(const float* __restrict__ src) {
    const int i = (blockIdx.x * 256 + threadIdx.x) * 4;
    float4 v = *(const float4*)(src + i);
    __nv_bfloat16 h0 = __float2bfloat16(v.x), h1 = __float2bfloat16(v.y);
    __nv_bfloat16 h2 = __float2bfloat16(v.z), h3 = __float2bfloat16(v.w);
    __nv_bfloat162 ph0; ph0.x = h0; ph0.y = h1;
    __nv_bfloat162 ph1; ph1.x = h2; ph1.y = h3;
    *(__nv_bfloat162*)&g_xhi[i] = ph0;
    *(__nv_bfloat162*)&g_xhi[i + 2] = ph1;
    __nv_bfloat162 pl0, pl1;
    pl0.x = __float2bfloat16(v.x - __bfloat162float(h0));
    pl0.y = __float2bfloat16(v.y - __bfloat162float(h1));
    pl1.x = __float2bfloat16(v.z - __bfloat162float(h2));
    pl1.y = __float2bfloat16(v.w - __bfloat162float(h3));
    *(__nv_bfloat162*)&g_xlo[i] = pl0;
    *(__nv_bfloat162*)&g_xlo[i + 2] = pl1;
}

__global__ void split_w(const float* __restrict__ src, int dir) {
    const int i = (blockIdx.x * 256 + threadIdx.x) * 4;
    float4 v = *(const float4*)(src + i);
    __nv_bfloat16* hi = g_whi[dir];
    __nv_bfloat16* lo = g_wlo[dir];
    __nv_bfloat16 h0 = __float2bfloat16(v.x), h1 = __float2bfloat16(v.y);
    __nv_bfloat16 h2 = __float2bfloat16(v.z), h3 = __float2bfloat16(v.w);
    __nv_bfloat162 ph0; ph0.x = h0; ph0.y = h1;
    __nv_bfloat162 ph1; ph1.x = h2; ph1.y = h3;
    *(__nv_bfloat162*)&hi[i] = ph0;
    *(__nv_bfloat162*)&hi[i + 2] = ph1;
    __nv_bfloat162 pl0, pl1;
    pl0.x = __float2bfloat16(v.x - __bfloat162float(h0));
    pl0.y = __float2bfloat16(v.y - __bfloat162float(h1));
    pl1.x = __float2bfloat16(v.z - __bfloat162float(h2));
    pl1.y = __float2bfloat16(v.w - __bfloat162float(h3));
    *(__nv_bfloat162*)&lo[i] = pl0;
    *(__nv_bfloat162*)&lo[i + 2] = pl1;
}

__global__ void init_bar() { g_ctr = 0u; }

// ============================================================================
// xproj via mma.sync split-bf16: g_xp[dir][m][n] = bias[n] + x[m,:]·W[n,:]
// CTA tile 128x128, 8 warps (2x4), warp tile 64x32, K chunks of 64 (cp.async).
// acc = Ahi*Bhi + Ahi*Blo + Alo*Bhi (fp32 accum).
// smem tiles [128][72] bf16 (pad 8 -> conflict-free ldmatrix).
// ============================================================================
#define APAD 72
#define TILE_ELEMS (128 * APAD)
#define XP_SMEM (4 * TILE_ELEMS * 2)

__global__ __launch_bounds__(256, 1)
void xproj_mma(const float* __restrict__ bias_f, const float* __restrict__ bias_b) {
    extern __shared__ __nv_bfloat16 smb[];
    __nv_bfloat16* Ah = smb;
    __nv_bfloat16* Al = smb + TILE_ELEMS;
    __nv_bfloat16* Bh = smb + 2 * TILE_ELEMS;
    __nv_bfloat16* Bl = smb + 3 * TILE_ELEMS;

    const int tid  = threadIdx.x;
    const int lane = tid & 31;
    const int warp = tid >> 5;
    const int m0   = blockIdx.x * 128;
    const int n0   = blockIdx.y * 128;
    const int dir  = blockIdx.z;
    const int wm   = (warp >> 2) * 64;   // warp m base in tile
    const int wn   = (warp & 3) * 32;    // warp n base in tile

    const __nv_bfloat16* __restrict__ gBh = g_whi[dir];
    const __nv_bfloat16* __restrict__ gBl = g_wlo[dir];
    const float* __restrict__ bias = dir ? bias_b : bias_f;

    const unsigned sAh = smem_u32(Ah), sAl = smem_u32(Al);
    const unsigned sBh = smem_u32(Bh), sBl = smem_u32(Bl);

    // ldmatrix lane address offsets
    const int r8 = lane & 7, grp = lane >> 3;
    const int a_row = r8 + ((grp & 1) << 3), a_col = ((grp >> 1) << 3);
    const int b_row = r8 + ((grp >> 1) << 3), b_col = ((grp & 1) << 3);

    // staging indices: 4 iters, 16B each, rows 0..127, 8 col-chunks
    const int st_row = tid >> 3;
    const int st_c8  = (tid & 7) << 3;

    float acc[4][4][4];
#pragma unroll
    for (int i = 0; i < 4; i++)
#pragma unroll
        for (int j = 0; j < 4; j++)
#pragma unroll
            for (int q = 0; q < 4; q++) acc[i][j][q] = 0.f;

    for (int c = 0; c < 8; c++) {
        const int k0 = c * 64;
#pragma unroll
        for (int it = 0; it < 4; it++) {
            const int row = st_row + (it << 5);
            const size_t ga = (size_t)(m0 + row) * 512 + k0 + st_c8;
            const size_t gb = (size_t)(n0 + row) * 512 + k0 + st_c8;
            const unsigned so = (unsigned)(row * APAD + st_c8) * 2u;
            cpa16(sAh + so, g_xhi + ga);
            cpa16(sAl + so, g_xlo + ga);
            cpa16(sBh + so, gBh + gb);
            cpa16(sBl + so, gBl + gb);
        }
        asm volatile("cp.async.commit_group;");
        asm volatile("cp.async.wait_group 0;");
        __syncthreads();

#pragma unroll
        for (int ks = 0; ks < 4; ks++) {
            const int k = ks * 16;
            unsigned ah[4][4], al[4][4], bh[4][2], bl[4][2];
#pragma unroll
            for (int i = 0; i < 4; i++) {
                const unsigned off =
                    (unsigned)((wm + i * 16 + a_row) * APAD + k + a_col) * 2u;
                ldm4(ah[i][0], ah[i][1], ah[i][2], ah[i][3], sAh + off);
                ldm4(al[i][0], al[i][1], al[i][2], al[i][3], sAl + off);
            }
#pragma unroll
            for (int jj = 0; jj < 2; jj++) {
                const unsigned off =
                    (unsigned)((wn + jj * 16 + b_row) * APAD + k + b_col) * 2u;
                unsigned t0, t1, t2, t3;
                ldm4(t0, t1, t2, t3, sBh + off);
                bh[jj * 2][0] = t0; bh[jj * 2][1] = t1;
                bh[jj * 2 + 1][0] = t2; bh[jj * 2 + 1][1] = t3;
                ldm4(t0, t1, t2, t3, sBl + off);
                bl[jj * 2][0] = t0; bl[jj * 2][1] = t1;
                bl[jj * 2 + 1][0] = t2; bl[jj * 2 + 1][1] = t3;
            }
#pragma unroll
            for (int i = 0; i < 4; i++)
#pragma unroll
                for (int j = 0; j < 4; j++) {
                    mma16816(acc[i][j], ah[i], bh[j]);
                    mma16816(acc[i][j], ah[i], bl[j]);
                    mma16816(acc[i][j], al[i], bh[j]);
                }
        }
        __syncthreads();
    }

    // epilogue: acc -> g_xp + bias
    const int tr = lane >> 2;
    const int tc = (lane & 3) << 1;
    float* __restrict__ dst = &g_xp[dir][0][0][0];
#pragma unroll
    for (int j = 0; j < 4; j++) {
        const int n = n0 + wn + j * 8 + tc;
        const float2 bv = *(const float2*)(bias + n);
#pragma unroll
        for (int i = 0; i < 4; i++) {
            const int m = m0 + wm + i * 16 + tr;
            float2 o0, o1;
            o0.x = acc[i][j][0] + bv.x; o0.y = acc[i][j][1] + bv.y;
            o1.x = acc[i][j][2] + bv.x; o1.y = acc[i][j][3] + bv.y;
            *(float2*)(dst + (size_t)m * GG + n) = o0;
            *(float2*)(dst + (size_t)(m + 8) * GG + n) = o1;
        }
    }
}

// ============================================================================
// Persistent bidirectional LSTM recurrence (unchanged from passing round 7)
// ============================================================================
__device__ __forceinline__ void load_hs(float* Hs, const float* src, int stride, int tid) {
#pragma unroll
    for (int i = 0; i < 32; i++) {
        int j  = tid + (i << 8);
        int b  = j >> 7;
        int k4 = j & 127;
        float4 v;
        const float* p = src + (size_t)b * stride + k4 * 4;
        asm volatile("ld.global.cg.v4.f32 {%0,%1,%2,%3}, [%4];"
                     : "=f"(v.x), "=f"(v.y), "=f"(v.z), "=f"(v.w) : "l"(p));
        *(float4*)(Hs + b * 516 + k4 * 4) = v;
    }
}

#define SMEM_FLOATS (16384 + 64*516 + 64*32 + 512)
#define SMEM_BYTES  (SMEM_FLOATS * 4)

__global__ __launch_bounds__(256, 1) void lstm_persist(const float* __restrict__ h0,
                                                       const float* __restrict__ c0,
                                                       const float* __restrict__ Whh_f,
                                                       const float* __restrict__ Whh_b,
                                                       float* __restrict__ out) {
    extern __shared__ float sm[];
    float* Ws  = sm;
    float* Hs  = sm + 16384;
    float* Gs  = Hs + 64 * 516;
    float* csh = Gs + 64 * 32;

    const int tid   = threadIdx.x;
    const int lane  = tid & 31;
    const int warp  = tid >> 5;
    const int cta   = blockIdx.x;
    const int dir   = cta >> 6;
    const int c0col = (cta & 63) << 3;
    const int ccmp  = warp << 2;
    const int gcol  = ((warp >> 1) << 9) + c0col + ((warp & 1) << 2);

    const float* __restrict__ Whh = dir ? Whh_b : Whh_f;
    const float* __restrict__ xpD = &g_xp[dir][0][0][0];

#pragma unroll
    for (int i = 0; i < 16; i++) {
        int j  = tid + (i << 8);
        int n  = j >> 7;
        int k4 = j & 127;
        int gn = ((n >> 3) << 9) + c0col + (n & 7);
        float4 w = *(const float4*)(Whh + (size_t)gn * HH + k4 * 4);
        int k = k4 * 4;
        Ws[(k + 0) * 32 + n] = w.x;
        Ws[(k + 1) * 32 + n] = w.y;
        Ws[(k + 2) * 32 + n] = w.z;
        Ws[(k + 3) * 32 + n] = w.w;
    }
    for (int p = tid; p < 512; p += 256) {
        int b = p >> 3, cc = p & 7;
        csh[p] = c0[(size_t)dir * BB * HH + b * HH + c0col + cc];
    }
    load_hs(Hs, h0 + (size_t)dir * BB * HH, HH, tid);
    __syncthreads();

    for (int step = 0; step < TT; step++) {
        const int t = dir ? (TT - 1 - step) : step;

        float a00 = 0.f, a01 = 0.f, a02 = 0.f, a03 = 0.f;
        float a10 = 0.f, a11 = 0.f, a12 = 0.f, a13 = 0.f;
        const float* hA = Hs + lane * 516;
        const float* hB = Hs + (lane + 32) * 516;
        const float* wP = Ws + ccmp;
#pragma unroll 4
        for (int k = 0; k < HH; k += 4) {
            const float4 ha = *(const float4*)(hA + k);
            const float4 hb = *(const float4*)(hB + k);
            const float4 w0 = *(const float4*)(wP + (k + 0) * 32);
            const float4 w1 = *(const float4*)(wP + (k + 1) * 32);
            const float4 w2 = *(const float4*)(wP + (k + 2) * 32);
            const float4 w3 = *(const float4*)(wP + (k + 3) * 32);
            a00 += ha.x * w0.x; a01 += ha.x * w0.y; a02 += ha.x * w0.z; a03 += ha.x * w0.w;
            a10 += hb.x * w0.x; a11 += hb.x * w0.y; a12 += hb.x * w0.z; a13 += hb.x * w0.w;
            a00 += ha.y * w1.x; a01 += ha.y * w1.y; a02 += ha.y * w1.z; a03 += ha.y * w1.w;
            a10 += hb.y * w1.x; a11 += hb.y * w1.y; a12 += hb.y * w1.z; a13 += hb.y * w1.w;
            a00 += ha.z * w2.x; a01 += ha.z * w2.y; a02 += ha.z * w2.z; a03 += ha.z * w2.w;
            a10 += hb.z * w2.x; a11 += hb.z * w2.y; a12 += hb.z * w2.z; a13 += hb.z * w2.w;
            a00 += ha.w * w3.x; a01 += ha.w * w3.y; a02 += ha.w * w3.z; a03 += ha.w * w3.w;
            a10 += hb.w * w3.x; a11 += hb.w * w3.y; a12 += hb.w * w3.z; a13 += hb.w * w3.w;
        }

        {
            const float* xpt = xpD + (size_t)t * BB * GG;
            float4 x0 = *(const float4*)(xpt + (size_t)lane * GG + gcol);
            float4 x1 = *(const float4*)(xpt + (size_t)(lane + 32) * GG + gcol);
            float4 gq;
            gq.x = a00 + x0.x; gq.y = a01 + x0.y; gq.z = a02 + x0.z; gq.w = a03 + x0.w;
            *(float4*)(Gs + lane * 32 + ccmp) = gq;
            gq.x = a10 + x1.x; gq.y = a11 + x1.y; gq.z = a12 + x1.z; gq.w = a13 + x1.w;
            *(float4*)(Gs + (lane + 32) * 32 + ccmp) = gq;
        }
        __syncthreads();

        for (int p = tid; p < 512; p += 256) {
            int b = p >> 3, cc = p & 7;
            const float gi = Gs[b * 32 + cc];
            const float gf = Gs[b * 32 + 8 + cc];
            const float gg = Gs[b * 32 + 16 + cc];
            const float go = Gs[b * 32 + 24 + cc];
            const float si = 1.f / (1.f + expf(-gi));
            const float sf = 1.f / (1.f + expf(-gf));
            const float tg = tanhf(gg);
            const float so = 1.f / (1.f + expf(-go));
            const float cn = sf * csh[p] + si * tg;
            csh[p] = cn;
            out[((size_t)t * BB + b) * (2 * HH) + (dir << 9) + c0col + cc] = so * tanhf(cn);
        }

        if (step == TT - 1) break;

        __threadfence();
        __syncthreads();
        if (tid == 0) {
            unsigned old;
            asm volatile("atom.add.release.gpu.global.u32 %0, [%1], 1;"
                         : "=r"(old) : "l"(&g_ctr) : "memory");
            const unsigned target = (unsigned)NCTA * (unsigned)(step + 1);
            unsigned v;
            do {
                asm volatile("ld.acquire.gpu.global.u32 %0, [%1];"
                             : "=r"(v) : "l"(&g_ctr) : "memory");
            } while (v < target);
        }
        __syncthreads();

        load_hs(Hs, out + (size_t)t * BB * (2 * HH) + (dir << 9), 2 * HH, tid);
        __syncthreads();
    }
}

// ============================================================================
extern "C" void kernel_launch(void* const* d_in, const int* in_sizes, int n_in,
                              void* d_out, int out_size) {
    const float* x      = (const float*)d_in[0];
    const float* h0     = (const float*)d_in[1];
    const float* c0     = (const float*)d_in[2];
    const float* W_ih_f = (const float*)d_in[3];
    const float* W_hh_f = (const float*)d_in[4];
    const float* b_f    = (const float*)d_in[5];
    const float* W_ih_b = (const float*)d_in[6];
    const float* W_hh_b = (const float*)d_in[7];
    const float* b_b    = (const float*)d_in[8];
    float* out = (float*)d_out;

    static int attr_set = 0;
    if (!attr_set) {
        cudaFuncSetAttribute(lstm_persist,
                             cudaFuncAttributeMaxDynamicSharedMemorySize, SMEM_BYTES);
        cudaFuncSetAttribute(xproj_mma,
                             cudaFuncAttributeMaxDynamicSharedMemorySize, XP_SMEM);
        attr_set = 1;
    }

    split_x<<<16384, 256>>>(x);
    split_w<<<1024, 256>>>(W_ih_f, 0);
    split_w<<<1024, 256>>>(W_ih_b, 1);
    init_bar<<<1, 1>>>();
    xproj_mma<<<dim3(256, 16, 2), 256, XP_SMEM>>>(b_f, b_b);
    lstm_persist<<<NCTA, 256, SMEM_BYTES>>>(h0, c0, W_hh_f, W_hh_b, out);
}

// round 13
// speedup vs baseline: 3.1289x; 1.6810x over previous
#include <cuda_runtime.h>
#include <cuda_bf16.h>
#include <cstdint>
#include <math.h>

#define TT 512
#define BB 64
#define II 512
#define HH 512
#define GG 2048   // 4*H
#define NCTA 128

// ---- scratch (static __device__ allocations only) ----
__device__ float         g_xp[2][TT][BB][GG];   // 512 MB x-projection (both dirs)
__device__ unsigned      g_ctr;                 // grid barrier counter
__device__ __nv_bfloat16 g_xhi[TT * BB * II];   // 32 MB
__device__ __nv_bfloat16 g_xlo[TT * BB * II];   // 32 MB
__device__ __nv_bfloat16 g_whi[2][GG * II];     // 4 MB
__device__ __nv_bfloat16 g_wlo[2][GG * II];     // 4 MB
__device__ __nv_bfloat16 g_hhi[2][BB][HH];      // 128 KB h state hi
__device__ __nv_bfloat16 g_hlo[2][BB][HH];      // 128 KB h state lo

// ============================================================================
// helpers
// ============================================================================
__device__ __forceinline__ unsigned smem_u32(const void* p) {
    unsigned a;
    asm("{ .reg .u64 t; cvta.to.shared.u64 t, %1; cvt.u32.u64 %0, t; }"
        : "=r"(a) : "l"(p));
    return a;
}
__device__ __forceinline__ void cpa16(unsigned dst, const void* src) {
    asm volatile("cp.async.cg.shared.global [%0], [%1], 16;" :: "r"(dst), "l"(src));
}
__device__ __forceinline__ void ldm4(unsigned& r0, unsigned& r1, unsigned& r2,
                                     unsigned& r3, unsigned addr) {
    asm volatile("ldmatrix.sync.aligned.m8n8.x4.shared.b16 {%0,%1,%2,%3}, [%4];"
                 : "=r"(r0), "=r"(r1), "=r"(r2), "=r"(r3) : "r"(addr));
}
__device__ __forceinline__ void mma16816(float* c, const unsigned* a, const unsigned* b) {
    asm volatile(
        "mma.sync.aligned.m16n8k16.row.col.f32.bf16.bf16.f32 "
        "{%0,%1,%2,%3}, {%4,%5,%6,%7}, {%8,%9}, {%0,%1,%2,%3};"
        : "+f"(c[0]), "+f"(c[1]), "+f"(c[2]), "+f"(c[3])
        : "r"(a[0]), "r"(a[1]), "r"(a[2]), "r"(a[3]), "r"(b[0]), "r"(b[1]));
}
__device__ __forceinline__ void split1(float v, __nv_bfloat16& h, __nv_bfloat16& l) {
    h = __float2bfloat16(v);
    l = __float2bfloat16(v - __bfloat162float(h));
}

// ============================================================================
// hi/lo bf16 split conversion kernels
// ============================================================================
__global__ void split_x(const float* __restrict__ src) {
    const int i = (blockIdx.x * 256 + threadIdx.x) * 4;
    float4 v = *(const float4*)(src + i);
#pragma unroll
    for (int q = 0; q < 4; q++) {
        float val = (&v.x)[q];
        split1(val, g_xhi[i + q], g_xlo[i + q]);
    }
}
__global__ void split_w(const float* __restrict__ src, int dir) {
    const int i = (blockIdx.x * 256 + threadIdx.x) * 4;
    float4 v = *(const float4*)(src + i);
#pragma unroll
    for (int q = 0; q < 4; q++) {
        float val = (&v.x)[q];
        split1(val, g_whi[dir][i + q], g_wlo[dir][i + q]);
    }
}
__global__ void conv_h0(const float* __restrict__ h0) {
    const int i = (blockIdx.x * 256 + threadIdx.x) * 4;   // 65536 total
    float4 v = *(const float4*)(h0 + i);
    __nv_bfloat16* hh = &g_hhi[0][0][0];
    __nv_bfloat16* hl = &g_hlo[0][0][0];
#pragma unroll
    for (int q = 0; q < 4; q++) {
        float val = (&v.x)[q];
        split1(val, hh[i + q], hl[i + q]);
    }
}
__global__ void init_bar() { g_ctr = 0u; }

// ============================================================================
// xproj via mma.sync split-bf16 (unchanged from passing round 11)
// ============================================================================
#define APAD 72
#define TILE_ELEMS (128 * APAD)
#define XP_SMEM (4 * TILE_ELEMS * 2)

__global__ __launch_bounds__(256, 1)
void xproj_mma(const float* __restrict__ bias_f, const float* __restrict__ bias_b) {
    extern __shared__ __nv_bfloat16 smb[];
    __nv_bfloat16* Ah = smb;
    __nv_bfloat16* Al = smb + TILE_ELEMS;
    __nv_bfloat16* Bh = smb + 2 * TILE_ELEMS;
    __nv_bfloat16* Bl = smb + 3 * TILE_ELEMS;

    const int tid  = threadIdx.x;
    const int lane = tid & 31;
    const int warp = tid >> 5;
    const int m0   = blockIdx.x * 128;
    const int n0   = blockIdx.y * 128;
    const int dir  = blockIdx.z;
    const int wm   = (warp >> 2) * 64;
    const int wn   = (warp & 3) * 32;

    const __nv_bfloat16* __restrict__ gBh = g_whi[dir];
    const __nv_bfloat16* __restrict__ gBl = g_wlo[dir];
    const float* __restrict__ bias = dir ? bias_b : bias_f;

    const unsigned sAh = smem_u32(Ah), sAl = smem_u32(Al);
    const unsigned sBh = smem_u32(Bh), sBl = smem_u32(Bl);

    const int r8 = lane & 7, grp = lane >> 3;
    const int a_row = r8 + ((grp & 1) << 3), a_col = ((grp >> 1) << 3);
    const int b_row = r8 + ((grp >> 1) << 3), b_col = ((grp & 1) << 3);

    const int st_row = tid >> 3;
    const int st_c8  = (tid & 7) << 3;

    float acc[4][4][4];
#pragma unroll
    for (int i = 0; i < 4; i++)
#pragma unroll
        for (int j = 0; j < 4; j++)
#pragma unroll
            for (int q = 0; q < 4; q++) acc[i][j][q] = 0.f;

    for (int c = 0; c < 8; c++) {
        const int k0 = c * 64;
#pragma unroll
        for (int it = 0; it < 4; it++) {
            const int row = st_row + (it << 5);
            const size_t ga = (size_t)(m0 + row) * 512 + k0 + st_c8;
            const size_t gb = (size_t)(n0 + row) * 512 + k0 + st_c8;
            const unsigned so = (unsigned)(row * APAD + st_c8) * 2u;
            cpa16(sAh + so, g_xhi + ga);
            cpa16(sAl + so, g_xlo + ga);
            cpa16(sBh + so, gBh + gb);
            cpa16(sBl + so, gBl + gb);
        }
        asm volatile("cp.async.commit_group;");
        asm volatile("cp.async.wait_group 0;");
        __syncthreads();

#pragma unroll
        for (int ks = 0; ks < 4; ks++) {
            const int k = ks * 16;
            unsigned ah[4][4], al[4][4], bh[4][2], bl[4][2];
#pragma unroll
            for (int i = 0; i < 4; i++) {
                const unsigned off =
                    (unsigned)((wm + i * 16 + a_row) * APAD + k + a_col) * 2u;
                ldm4(ah[i][0], ah[i][1], ah[i][2], ah[i][3], sAh + off);
                ldm4(al[i][0], al[i][1], al[i][2], al[i][3], sAl + off);
            }
#pragma unroll
            for (int jj = 0; jj < 2; jj++) {
                const unsigned off =
                    (unsigned)((wn + jj * 16 + b_row) * APAD + k + b_col) * 2u;
                unsigned t0, t1, t2, t3;
                ldm4(t0, t1, t2, t3, sBh + off);
                bh[jj * 2][0] = t0; bh[jj * 2][1] = t1;
                bh[jj * 2 + 1][0] = t2; bh[jj * 2 + 1][1] = t3;
                ldm4(t0, t1, t2, t3, sBl + off);
                bl[jj * 2][0] = t0; bl[jj * 2][1] = t1;
                bl[jj * 2 + 1][0] = t2; bl[jj * 2 + 1][1] = t3;
            }
#pragma unroll
            for (int i = 0; i < 4; i++)
#pragma unroll
                for (int j = 0; j < 4; j++) {
                    mma16816(acc[i][j], ah[i], bh[j]);
                    mma16816(acc[i][j], ah[i], bl[j]);
                    mma16816(acc[i][j], al[i], bh[j]);
                }
        }
        __syncthreads();
    }

    const int tr = lane >> 2;
    const int tc = (lane & 3) << 1;
    float* __restrict__ dst = &g_xp[dir][0][0][0];
#pragma unroll
    for (int j = 0; j < 4; j++) {
        const int n = n0 + wn + j * 8 + tc;
        const float2 bv = *(const float2*)(bias + n);
#pragma unroll
        for (int i = 0; i < 4; i++) {
            const int m = m0 + wm + i * 16 + tr;
            float2 o0, o1;
            o0.x = acc[i][j][0] + bv.x; o0.y = acc[i][j][1] + bv.y;
            o1.x = acc[i][j][2] + bv.x; o1.y = acc[i][j][3] + bv.y;
            *(float2*)(dst + (size_t)m * GG + n) = o0;
            *(float2*)(dst + (size_t)(m + 8) * GG + n) = o1;
        }
    }
}

// ============================================================================
// Persistent recurrence with split-bf16 mma.sync.
// 128 CTAs: dir = cta>>6, c0col = (cta&63)*8 (8 h-cols -> 32 compact gate cols,
// compact col cc: gate g = cc>>3, hcol = c0col + (cc&7)).
// smem: Wh/Wl [32][520] bf16 resident; Hh/Hl [64][520] bf16 per-step; Gs; csh.
// Warp tile m16n16: wm = (warp>>1)*16, wn = (warp&1)*16. 3-pass hi/lo mma.
// ============================================================================
#define HPAD 520
#define W_ELE (32 * HPAD)
#define H_ELE (64 * HPAD)
#define RS_SMEM ((2 * W_ELE + 2 * H_ELE) * 2 + 64 * 32 * 4 + 512 * 4)

__global__ __launch_bounds__(256, 1) void lstm_mma(const float* __restrict__ c0,
                                                   const float* __restrict__ Whh_f,
                                                   const float* __restrict__ Whh_b,
                                                   float* __restrict__ out) {
    extern __shared__ __nv_bfloat16 smc[];
    __nv_bfloat16* Wh = smc;                 // [32][520]
    __nv_bfloat16* Wl = Wh + W_ELE;
    __nv_bfloat16* Hh = Wl + W_ELE;          // [64][520]
    __nv_bfloat16* Hl = Hh + H_ELE;
    float* Gs  = (float*)(Hl + H_ELE);       // [64][32]
    float* csh = Gs + 64 * 32;               // [512]

    const int tid   = threadIdx.x;
    const int lane  = tid & 31;
    const int warp  = tid >> 5;
    const int cta   = blockIdx.x;
    const int dir   = cta >> 6;
    const int c0col = (cta & 63) << 3;
    const int wm    = (warp >> 1) << 4;      // 0,16,32,48
    const int wn    = (warp & 1) << 4;       // 0,16

    const float* __restrict__ Whh = dir ? Whh_b : Whh_f;
    const float* __restrict__ xpD = &g_xp[dir][0][0][0];
    const __nv_bfloat16* __restrict__ gHh = &g_hhi[dir][0][0];
    const __nv_bfloat16* __restrict__ gHl = &g_hlo[dir][0][0];

    const unsigned sWh = smem_u32(Wh), sWl = smem_u32(Wl);
    const unsigned sHh = smem_u32(Hh), sHl = smem_u32(Hl);

    const int r8 = lane & 7, grp = lane >> 3;
    const int a_row = r8 + ((grp & 1) << 3), a_col = ((grp >> 1) << 3);
    const int b_row = r8 + ((grp >> 1) << 3), b_col = ((grp & 1) << 3);

    // epilogue / xp mapping (constant over steps)
    const int tr  = lane >> 2;
    const int r0  = wm + tr, r1 = r0 + 8;
    const int cc0 = wn + ((lane & 3) << 1);          // j=0 compact col
    const int cc1 = cc0 + 8;                         // j=1 compact col
    const int ng0 = ((cc0 >> 3) << 9) + c0col + (cc0 & 7);
    const int ng1 = ((cc1 >> 3) << 9) + c0col + (cc1 & 7);

    // ---- W_hh slice -> smem bf16 hi/lo ----
#pragma unroll
    for (int i = 0; i < 16; i++) {
        int j  = tid + (i << 8);              // 0..4095 float4s
        int cc = j >> 7;
        int k4 = (j & 127) << 2;
        int gn = ((cc >> 3) << 9) + c0col + (cc & 7);
        float4 w = *(const float4*)(Whh + (size_t)gn * HH + k4);
#pragma unroll
        for (int q = 0; q < 4; q++)
            split1((&w.x)[q], Wh[cc * HPAD + k4 + q], Wl[cc * HPAD + k4 + q]);
    }
    for (int p = tid; p < 512; p += 256) {
        int b = p >> 3, cc = p & 7;
        csh[p] = c0[(size_t)dir * BB * HH + b * HH + c0col + cc];
    }
    // ---- h(0) hi/lo -> smem ----
#pragma unroll
    for (int i = 0; i < 16; i++) {
        int j = tid + (i << 8);               // 4096 16B chunks per buffer
        int b = j >> 6, c16 = (j & 63) << 3;  // 64 chunks/row, col in bf16
        unsigned so = (unsigned)(b * HPAD + c16) * 2u;
        cpa16(sHh + so, gHh + (size_t)b * HH + c16);
        cpa16(sHl + so, gHl + (size_t)b * HH + c16);
    }
    asm volatile("cp.async.commit_group;");
    asm volatile("cp.async.wait_group 0;");
    __syncthreads();

    for (int step = 0; step < TT; step++) {
        const int t = dir ? (TT - 1 - step) : step;

        // prefetch xp for this thread's accumulator cells (hidden under MMAs)
        const float* xpt = xpD + (size_t)t * BB * GG;
        const float2 xv00 = *(const float2*)(xpt + (size_t)r0 * GG + ng0);
        const float2 xv01 = *(const float2*)(xpt + (size_t)r1 * GG + ng0);
        const float2 xv10 = *(const float2*)(xpt + (size_t)r0 * GG + ng1);
        const float2 xv11 = *(const float2*)(xpt + (size_t)r1 * GG + ng1);

        float acc0[4] = {0.f, 0.f, 0.f, 0.f};
        float acc1[4] = {0.f, 0.f, 0.f, 0.f};

#pragma unroll 4
        for (int ks = 0; ks < 32; ks++) {
            const int k = ks << 4;
            unsigned ah[4], al[4], bh0[2], bh1[2], bl0[2], bl1[2];
            const unsigned aoff = (unsigned)((wm + a_row) * HPAD + k + a_col) * 2u;
            ldm4(ah[0], ah[1], ah[2], ah[3], sHh + aoff);
            ldm4(al[0], al[1], al[2], al[3], sHl + aoff);
            const unsigned boff = (unsigned)((wn + b_row) * HPAD + k + b_col) * 2u;
            unsigned t0, t1, t2, t3;
            ldm4(t0, t1, t2, t3, sWh + boff);
            bh0[0] = t0; bh0[1] = t1; bh1[0] = t2; bh1[1] = t3;
            ldm4(t0, t1, t2, t3, sWl + boff);
            bl0[0] = t0; bl0[1] = t1; bl1[0] = t2; bl1[1] = t3;
            mma16816(acc0, ah, bh0);
            mma16816(acc0, ah, bl0);
            mma16816(acc0, al, bh0);
            mma16816(acc1, ah, bh1);
            mma16816(acc1, ah, bl1);
            mma16816(acc1, al, bh1);
        }

        // epilogue -> Gs
        {
            float2 v;
            v.x = acc0[0] + xv00.x; v.y = acc0[1] + xv00.y;
            *(float2*)(Gs + r0 * 32 + cc0) = v;
            v.x = acc0[2] + xv01.x; v.y = acc0[3] + xv01.y;
            *(float2*)(Gs + r1 * 32 + cc0) = v;
            v.x = acc1[0] + xv10.x; v.y = acc1[1] + xv10.y;
            *(float2*)(Gs + r0 * 32 + cc1) = v;
            v.x = acc1[2] + xv11.x; v.y = acc1[3] + xv11.y;
            *(float2*)(Gs + r1 * 32 + cc1) = v;
        }
        __syncthreads();

        // cell update + write h (fp32 out, bf16 hi/lo state)
        for (int p = tid; p < 512; p += 256) {
            int b = p >> 3, cc = p & 7;
            const float gi = Gs[b * 32 + cc];
            const float gf = Gs[b * 32 + 8 + cc];
            const float gg = Gs[b * 32 + 16 + cc];
            const float go = Gs[b * 32 + 24 + cc];
            const float si = 1.f / (1.f + expf(-gi));
            const float sf = 1.f / (1.f + expf(-gf));
            const float tg = tanhf(gg);
            const float so = 1.f / (1.f + expf(-go));
            const float cn = sf * csh[p] + si * tg;
            csh[p] = cn;
            const float hv = so * tanhf(cn);
            out[((size_t)t * BB + b) * (2 * HH) + (dir << 9) + c0col + cc] = hv;
            const int hidx = b * HH + c0col + cc;
            __nv_bfloat16 hi, lo;
            split1(hv, hi, lo);
            g_hhi[dir][0][hidx] = hi;
            g_hlo[dir][0][hidx] = lo;
        }

        if (step == TT - 1) break;

        // ---- grid barrier (release/acquire) ----
        __threadfence();
        __syncthreads();
        if (tid == 0) {
            unsigned old;
            asm volatile("atom.add.release.gpu.global.u32 %0, [%1], 1;"
                         : "=r"(old) : "l"(&g_ctr) : "memory");
            const unsigned target = (unsigned)NCTA * (unsigned)(step + 1);
            unsigned v;
            do {
                asm volatile("ld.acquire.gpu.global.u32 %0, [%1];"
                             : "=r"(v) : "l"(&g_ctr) : "memory");
            } while (v < target);
        }
        __syncthreads();

        // ---- reload h hi/lo ----
#pragma unroll
        for (int i = 0; i < 16; i++) {
            int j = tid + (i << 8);
            int b = j >> 6, c16 = (j & 63) << 3;
            unsigned so = (unsigned)(b * HPAD + c16) * 2u;
            cpa16(sHh + so, gHh + (size_t)b * HH + c16);
            cpa16(sHl + so, gHl + (size_t)b * HH + c16);
        }
        asm volatile("cp.async.commit_group;");
        asm volatile("cp.async.wait_group 0;");
        __syncthreads();
    }
}

// ============================================================================
extern "C" void kernel_launch(void* const* d_in, const int* in_sizes, int n_in,
                              void* d_out, int out_size) {
    const float* x      = (const float*)d_in[0];
    const float* h0     = (const float*)d_in[1];
    const float* c0     = (const float*)d_in[2];
    const float* W_ih_f = (const float*)d_in[3];
    const float* W_hh_f = (const float*)d_in[4];
    const float* b_f    = (const float*)d_in[5];
    const float* W_ih_b = (const float*)d_in[6];
    const float* W_hh_b = (const float*)d_in[7];
    const float* b_b    = (const float*)d_in[8];
    float* out = (float*)d_out;

    static int attr_set = 0;
    if (!attr_set) {
        cudaFuncSetAttribute(xproj_mma,
                             cudaFuncAttributeMaxDynamicSharedMemorySize, XP_SMEM);
        cudaFuncSetAttribute(lstm_mma,
                             cudaFuncAttributeMaxDynamicSharedMemorySize, RS_SMEM);
        attr_set = 1;
    }

    split_x<<<16384, 256>>>(x);
    split_w<<<1024, 256>>>(W_ih_f, 0);
    split_w<<<1024, 256>>>(W_ih_b, 1);
    conv_h0<<<64, 256>>>(h0);
    init_bar<<<1, 1>>>();
    xproj_mma<<<dim3(256, 16, 2), 256, XP_SMEM>>>(b_f, b_b);
    lstm_mma<<<NCTA, 256, RS_SMEM>>>(c0, W_hh_f, W_hh_b, out);
}

// round 14
// speedup vs baseline: 3.3118x; 1.0585x over previous
#include <cuda_runtime.h>
#include <cuda_bf16.h>
#include <cstdint>
#include <math.h>

#define TT 512
#define BB 64
#define II 512
#define HH 512
#define GG 2048   // 4*H
#define NCTA 128

// ---- scratch (static __device__ allocations only) ----
__device__ float         g_xp[2][TT][BB][GG];   // 512 MB x-projection (both dirs)
__device__ unsigned      g_ctr2[2];             // per-direction barrier counters
__device__ __nv_bfloat16 g_xhi[TT * BB * II];   // 32 MB
__device__ __nv_bfloat16 g_xlo[TT * BB * II];   // 32 MB
__device__ __nv_bfloat16 g_whi[2][GG * II];     // 4 MB
__device__ __nv_bfloat16 g_wlo[2][GG * II];     // 4 MB
__device__ __nv_bfloat16 g_hhi[2][BB][HH];      // 128 KB h state hi
__device__ __nv_bfloat16 g_hlo[2][BB][HH];      // 128 KB h state lo

// ============================================================================
// helpers
// ============================================================================
__device__ __forceinline__ unsigned smem_u32(const void* p) {
    unsigned a;
    asm("{ .reg .u64 t; cvta.to.shared.u64 t, %1; cvt.u32.u64 %0, t; }"
        : "=r"(a) : "l"(p));
    return a;
}
__device__ __forceinline__ void cpa16(unsigned dst, const void* src) {
    asm volatile("cp.async.cg.shared.global [%0], [%1], 16;" :: "r"(dst), "l"(src));
}
__device__ __forceinline__ void ldm4(unsigned& r0, unsigned& r1, unsigned& r2,
                                     unsigned& r3, unsigned addr) {
    asm volatile("ldmatrix.sync.aligned.m8n8.x4.shared.b16 {%0,%1,%2,%3}, [%4];"
                 : "=r"(r0), "=r"(r1), "=r"(r2), "=r"(r3) : "r"(addr));
}
__device__ __forceinline__ void mma16816(float* c, const unsigned* a, const unsigned* b) {
    asm volatile(
        "mma.sync.aligned.m16n8k16.row.col.f32.bf16.bf16.f32 "
        "{%0,%1,%2,%3}, {%4,%5,%6,%7}, {%8,%9}, {%0,%1,%2,%3};"
        : "+f"(c[0]), "+f"(c[1]), "+f"(c[2]), "+f"(c[3])
        : "r"(a[0]), "r"(a[1]), "r"(a[2]), "r"(a[3]), "r"(b[0]), "r"(b[1]));
}
__device__ __forceinline__ void split1(float v, __nv_bfloat16& h, __nv_bfloat16& l) {
    h = __float2bfloat16(v);
    l = __float2bfloat16(v - __bfloat162float(h));
}

// ============================================================================
// hi/lo bf16 split conversion kernels
// ============================================================================
__global__ void split_x(const float* __restrict__ src) {
    const int i = (blockIdx.x * 256 + threadIdx.x) * 4;
    float4 v = *(const float4*)(src + i);
#pragma unroll
    for (int q = 0; q < 4; q++) {
        float val = (&v.x)[q];
        split1(val, g_xhi[i + q], g_xlo[i + q]);
    }
}
__global__ void split_w(const float* __restrict__ src, int dir) {
    const int i = (blockIdx.x * 256 + threadIdx.x) * 4;
    float4 v = *(const float4*)(src + i);
#pragma unroll
    for (int q = 0; q < 4; q++) {
        float val = (&v.x)[q];
        split1(val, g_whi[dir][i + q], g_wlo[dir][i + q]);
    }
}
__global__ void conv_h0(const float* __restrict__ h0) {
    const int i = (blockIdx.x * 256 + threadIdx.x) * 4;   // 65536 total
    float4 v = *(const float4*)(h0 + i);
    __nv_bfloat16* hh = &g_hhi[0][0][0];
    __nv_bfloat16* hl = &g_hlo[0][0][0];
#pragma unroll
    for (int q = 0; q < 4; q++) {
        float val = (&v.x)[q];
        split1(val, hh[i + q], hl[i + q]);
    }
}
__global__ void init_bar() { g_ctr2[0] = 0u; g_ctr2[1] = 0u; }

// ============================================================================
// xproj via mma.sync split-bf16, double-buffered cp.async pipeline.
// CTA tile 128x128, 8 warps (2x4), warp tile 64x32, K chunks of 64.
// ============================================================================
#define APAD 72
#define TILE_ELEMS (128 * APAD)
#define TILE_B (TILE_ELEMS * 2)        // bytes per tile
#define STG_B  (4 * TILE_B)            // bytes per stage (Ah,Al,Bh,Bl)
#define XP_SMEM (2 * STG_B)

__global__ __launch_bounds__(256, 1)
void xproj_mma(const float* __restrict__ bias_f, const float* __restrict__ bias_b) {
    extern __shared__ __nv_bfloat16 smb[];

    const int tid  = threadIdx.x;
    const int lane = tid & 31;
    const int warp = tid >> 5;
    const int m0   = blockIdx.x * 128;
    const int n0   = blockIdx.y * 128;
    const int dir  = blockIdx.z;
    const int wm   = (warp >> 2) * 64;
    const int wn   = (warp & 3) * 32;

    const __nv_bfloat16* __restrict__ gBh = g_whi[dir];
    const __nv_bfloat16* __restrict__ gBl = g_wlo[dir];
    const float* __restrict__ bias = dir ? bias_b : bias_f;

    const unsigned sbase = smem_u32(smb);

    const int r8 = lane & 7, grp = lane >> 3;
    const int a_row = r8 + ((grp & 1) << 3), a_col = ((grp >> 1) << 3);
    const int b_row = r8 + ((grp >> 1) << 3), b_col = ((grp & 1) << 3);

    const int st_row = tid >> 3;
    const int st_c8  = (tid & 7) << 3;

    float acc[4][4][4];
#pragma unroll
    for (int i = 0; i < 4; i++)
#pragma unroll
        for (int j = 0; j < 4; j++)
#pragma unroll
            for (int q = 0; q < 4; q++) acc[i][j][q] = 0.f;

    // stage load: chunk c -> stage s
    auto load_chunk = [&](int c, int s) {
        const int k0 = c * 64;
        const unsigned sb = sbase + (unsigned)s * STG_B;
#pragma unroll
        for (int it = 0; it < 4; it++) {
            const int row = st_row + (it << 5);
            const size_t ga = (size_t)(m0 + row) * 512 + k0 + st_c8;
            const size_t gb = (size_t)(n0 + row) * 512 + k0 + st_c8;
            const unsigned so = (unsigned)(row * APAD + st_c8) * 2u;
            cpa16(sb + so, g_xhi + ga);
            cpa16(sb + TILE_B + so, g_xlo + ga);
            cpa16(sb + 2 * TILE_B + so, gBh + gb);
            cpa16(sb + 3 * TILE_B + so, gBl + gb);
        }
        asm volatile("cp.async.commit_group;");
    };

    load_chunk(0, 0);

    for (int c = 0; c < 8; c++) {
        const int s = c & 1;
        if (c < 7) load_chunk(c + 1, s ^ 1);
        if (c < 7) asm volatile("cp.async.wait_group 1;");
        else       asm volatile("cp.async.wait_group 0;");
        __syncthreads();

        const unsigned sAh = sbase + (unsigned)s * STG_B;
        const unsigned sAl = sAh + TILE_B;
        const unsigned sBh = sAh + 2 * TILE_B;
        const unsigned sBl = sAh + 3 * TILE_B;

#pragma unroll
        for (int ks = 0; ks < 4; ks++) {
            const int k = ks * 16;
            unsigned ah[4][4], al[4][4], bh[4][2], bl[4][2];
#pragma unroll
            for (int i = 0; i < 4; i++) {
                const unsigned off =
                    (unsigned)((wm + i * 16 + a_row) * APAD + k + a_col) * 2u;
                ldm4(ah[i][0], ah[i][1], ah[i][2], ah[i][3], sAh + off);
                ldm4(al[i][0], al[i][1], al[i][2], al[i][3], sAl + off);
            }
#pragma unroll
            for (int jj = 0; jj < 2; jj++) {
                const unsigned off =
                    (unsigned)((wn + jj * 16 + b_row) * APAD + k + b_col) * 2u;
                unsigned t0, t1, t2, t3;
                ldm4(t0, t1, t2, t3, sBh + off);
                bh[jj * 2][0] = t0; bh[jj * 2][1] = t1;
                bh[jj * 2 + 1][0] = t2; bh[jj * 2 + 1][1] = t3;
                ldm4(t0, t1, t2, t3, sBl + off);
                bl[jj * 2][0] = t0; bl[jj * 2][1] = t1;
                bl[jj * 2 + 1][0] = t2; bl[jj * 2 + 1][1] = t3;
            }
#pragma unroll
            for (int i = 0; i < 4; i++)
#pragma unroll
                for (int j = 0; j < 4; j++) {
                    mma16816(acc[i][j], ah[i], bh[j]);
                    mma16816(acc[i][j], ah[i], bl[j]);
                    mma16816(acc[i][j], al[i], bh[j]);
                }
        }
        __syncthreads();
    }

    const int tr = lane >> 2;
    const int tc = (lane & 3) << 1;
    float* __restrict__ dst = &g_xp[dir][0][0][0];
#pragma unroll
    for (int j = 0; j < 4; j++) {
        const int n = n0 + wn + j * 8 + tc;
        const float2 bv = *(const float2*)(bias + n);
#pragma unroll
        for (int i = 0; i < 4; i++) {
            const int m = m0 + wm + i * 16 + tr;
            float2 o0, o1;
            o0.x = acc[i][j][0] + bv.x; o0.y = acc[i][j][1] + bv.y;
            o1.x = acc[i][j][2] + bv.x; o1.y = acc[i][j][3] + bv.y;
            *(float2*)(dst + (size_t)m * GG + n) = o0;
            *(float2*)(dst + (size_t)(m + 8) * GG + n) = o1;
        }
    }
}

// ============================================================================
// Persistent recurrence with split-bf16 mma.sync (per-direction barriers).
// ============================================================================
#define HPAD 520
#define W_ELE (32 * HPAD)
#define H_ELE (64 * HPAD)
#define RS_SMEM ((2 * W_ELE + 2 * H_ELE) * 2 + 64 * 32 * 4 + 512 * 4)

__global__ __launch_bounds__(256, 1) void lstm_mma(const float* __restrict__ c0,
                                                   const float* __restrict__ Whh_f,
                                                   const float* __restrict__ Whh_b,
                                                   float* __restrict__ out) {
    extern __shared__ __nv_bfloat16 smc[];
    __nv_bfloat16* Wh = smc;                 // [32][520]
    __nv_bfloat16* Wl = Wh + W_ELE;
    __nv_bfloat16* Hh = Wl + W_ELE;          // [64][520]
    __nv_bfloat16* Hl = Hh + H_ELE;
    float* Gs  = (float*)(Hl + H_ELE);       // [64][32]
    float* csh = Gs + 64 * 32;               // [512]

    const int tid   = threadIdx.x;
    const int lane  = tid & 31;
    const int warp  = tid >> 5;
    const int cta   = blockIdx.x;
    const int dir   = cta >> 6;
    const int c0col = (cta & 63) << 3;
    const int wm    = (warp >> 1) << 4;      // 0,16,32,48
    const int wn    = (warp & 1) << 4;       // 0,16

    const float* __restrict__ Whh = dir ? Whh_b : Whh_f;
    const float* __restrict__ xpD = &g_xp[dir][0][0][0];
    const __nv_bfloat16* __restrict__ gHh = &g_hhi[dir][0][0];
    const __nv_bfloat16* __restrict__ gHl = &g_hlo[dir][0][0];
    unsigned* const ctr = &g_ctr2[dir];

    const unsigned sWh = smem_u32(Wh), sWl = smem_u32(Wl);
    const unsigned sHh = smem_u32(Hh), sHl = smem_u32(Hl);

    const int r8 = lane & 7, grp = lane >> 3;
    const int a_row = r8 + ((grp & 1) << 3), a_col = ((grp >> 1) << 3);
    const int b_row = r8 + ((grp >> 1) << 3), b_col = ((grp & 1) << 3);

    const int tr  = lane >> 2;
    const int r0  = wm + tr, r1 = r0 + 8;
    const int cc0 = wn + ((lane & 3) << 1);
    const int cc1 = cc0 + 8;
    const int ng0 = ((cc0 >> 3) << 9) + c0col + (cc0 & 7);
    const int ng1 = ((cc1 >> 3) << 9) + c0col + (cc1 & 7);

    // ---- W_hh slice -> smem bf16 hi/lo ----
#pragma unroll
    for (int i = 0; i < 16; i++) {
        int j  = tid + (i << 8);
        int cc = j >> 7;
        int k4 = (j & 127) << 2;
        int gn = ((cc >> 3) << 9) + c0col + (cc & 7);
        float4 w = *(const float4*)(Whh + (size_t)gn * HH + k4);
#pragma unroll
        for (int q = 0; q < 4; q++)
            split1((&w.x)[q], Wh[cc * HPAD + k4 + q], Wl[cc * HPAD + k4 + q]);
    }
    for (int p = tid; p < 512; p += 256) {
        int b = p >> 3, cc = p & 7;
        csh[p] = c0[(size_t)dir * BB * HH + b * HH + c0col + cc];
    }
    // ---- h(0) hi/lo -> smem ----
#pragma unroll
    for (int i = 0; i < 16; i++) {
        int j = tid + (i << 8);
        int b = j >> 6, c16 = (j & 63) << 3;
        unsigned so = (unsigned)(b * HPAD + c16) * 2u;
        cpa16(sHh + so, gHh + (size_t)b * HH + c16);
        cpa16(sHl + so, gHl + (size_t)b * HH + c16);
    }
    asm volatile("cp.async.commit_group;");
    asm volatile("cp.async.wait_group 0;");
    __syncthreads();

    for (int step = 0; step < TT; step++) {
        const int t = dir ? (TT - 1 - step) : step;

        const float* xpt = xpD + (size_t)t * BB * GG;
        const float2 xv00 = *(const float2*)(xpt + (size_t)r0 * GG + ng0);
        const float2 xv01 = *(const float2*)(xpt + (size_t)r1 * GG + ng0);
        const float2 xv10 = *(const float2*)(xpt + (size_t)r0 * GG + ng1);
        const float2 xv11 = *(const float2*)(xpt + (size_t)r1 * GG + ng1);

        float acc0[4] = {0.f, 0.f, 0.f, 0.f};
        float acc1[4] = {0.f, 0.f, 0.f, 0.f};

#pragma unroll 4
        for (int ks = 0; ks < 32; ks++) {
            const int k = ks << 4;
            unsigned ah[4], al[4], bh0[2], bh1[2], bl0[2], bl1[2];
            const unsigned aoff = (unsigned)((wm + a_row) * HPAD + k + a_col) * 2u;
            ldm4(ah[0], ah[1], ah[2], ah[3], sHh + aoff);
            ldm4(al[0], al[1], al[2], al[3], sHl + aoff);
            const unsigned boff = (unsigned)((wn + b_row) * HPAD + k + b_col) * 2u;
            unsigned t0, t1, t2, t3;
            ldm4(t0, t1, t2, t3, sWh + boff);
            bh0[0] = t0; bh0[1] = t1; bh1[0] = t2; bh1[1] = t3;
            ldm4(t0, t1, t2, t3, sWl + boff);
            bl0[0] = t0; bl0[1] = t1; bl1[0] = t2; bl1[1] = t3;
            mma16816(acc0, ah, bh0);
            mma16816(acc0, ah, bl0);
            mma16816(acc0, al, bh0);
            mma16816(acc1, ah, bh1);
            mma16816(acc1, ah, bl1);
            mma16816(acc1, al, bh1);
        }

        {
            float2 v;
            v.x = acc0[0] + xv00.x; v.y = acc0[1] + xv00.y;
            *(float2*)(Gs + r0 * 32 + cc0) = v;
            v.x = acc0[2] + xv01.x; v.y = acc0[3] + xv01.y;
            *(float2*)(Gs + r1 * 32 + cc0) = v;
            v.x = acc1[0] + xv10.x; v.y = acc1[1] + xv10.y;
            *(float2*)(Gs + r0 * 32 + cc1) = v;
            v.x = acc1[2] + xv11.x; v.y = acc1[3] + xv11.y;
            *(float2*)(Gs + r1 * 32 + cc1) = v;
        }
        __syncthreads();

        for (int p = tid; p < 512; p += 256) {
            int b = p >> 3, cc = p & 7;
            const float gi = Gs[b * 32 + cc];
            const float gf = Gs[b * 32 + 8 + cc];
            const float gg = Gs[b * 32 + 16 + cc];
            const float go = Gs[b * 32 + 24 + cc];
            const float si = 1.f / (1.f + expf(-gi));
            const float sf = 1.f / (1.f + expf(-gf));
            const float tg = tanhf(gg);
            const float so = 1.f / (1.f + expf(-go));
            const float cn = sf * csh[p] + si * tg;
            csh[p] = cn;
            const float hv = so * tanhf(cn);
            out[((size_t)t * BB + b) * (2 * HH) + (dir << 9) + c0col + cc] = hv;
            const int hidx = b * HH + c0col + cc;
            __nv_bfloat16 hi, lo;
            split1(hv, hi, lo);
            g_hhi[dir][0][hidx] = hi;
            g_hlo[dir][0][hidx] = lo;
        }

        if (step == TT - 1) break;

        // ---- per-direction grid barrier (release/acquire, 64 CTAs) ----
        __threadfence();
        __syncthreads();
        if (tid == 0) {
            unsigned old;
            asm volatile("atom.add.release.gpu.global.u32 %0, [%1], 1;"
                         : "=r"(old) : "l"(ctr) : "memory");
            const unsigned target = 64u * (unsigned)(step + 1);
            unsigned v;
            do {
                asm volatile("ld.acquire.gpu.global.u32 %0, [%1];"
                             : "=r"(v) : "l"(ctr) : "memory");
            } while (v < target);
        }
        __syncthreads();

        // ---- reload h hi/lo ----
#pragma unroll
        for (int i = 0; i < 16; i++) {
            int j = tid + (i << 8);
            int b = j >> 6, c16 = (j & 63) << 3;
            unsigned so = (unsigned)(b * HPAD + c16) * 2u;
            cpa16(sHh + so, gHh + (size_t)b * HH + c16);
            cpa16(sHl + so, gHl + (size_t)b * HH + c16);
        }
        asm volatile("cp.async.commit_group;");
        asm volatile("cp.async.wait_group 0;");
        __syncthreads();
    }
}

// ============================================================================
extern "C" void kernel_launch(void* const* d_in, const int* in_sizes, int n_in,
                              void* d_out, int out_size) {
    const float* x      = (const float*)d_in[0];
    const float* h0     = (const float*)d_in[1];
    const float* c0     = (const float*)d_in[2];
    const float* W_ih_f = (const float*)d_in[3];
    const float* W_hh_f = (const float*)d_in[4];
    const float* b_f    = (const float*)d_in[5];
    const float* W_ih_b = (const float*)d_in[6];
    const float* W_hh_b = (const float*)d_in[7];
    const float* b_b    = (const float*)d_in[8];
    float* out = (float*)d_out;

    static int attr_set = 0;
    if (!attr_set) {
        cudaFuncSetAttribute(xproj_mma,
                             cudaFuncAttributeMaxDynamicSharedMemorySize, XP_SMEM);
        cudaFuncSetAttribute(lstm_mma,
                             cudaFuncAttributeMaxDynamicSharedMemorySize, RS_SMEM);
        attr_set = 1;
    }

    split_x<<<16384, 256>>>(x);
    split_w<<<1024, 256>>>(W_ih_f, 0);
    split_w<<<1024, 256>>>(W_ih_b, 1);
    conv_h0<<<64, 256>>>(h0);
    init_bar<<<1, 1>>>();
    xproj_mma<<<dim3(256, 16, 2), 256, XP_SMEM>>>(b_f, b_b);
    lstm_mma<<<NCTA, 256, RS_SMEM>>>(c0, W_hh_f, W_hh_b, out);
}